// round 4
// baseline (speedup 1.0000x reference)
#include <cuda_runtime.h>
#include <cuda_bf16.h>
#include <cstdint>

// ---------------------------------------------------------------------------
// 2-layer GRU (H=32, INPUT=4, B=4096, S=512) + FC(32->32) + FC(32->1)
//
// Warp per batch row, lane per hidden unit.
// - Gate dot products use packed fma.rn.f32x2 over (even j, odd j) pairs:
//   weight pairs are contiguous in the weight row, operand pairs are
//   contiguous in the broadcast h buffer -> no splat/pack instructions.
// - h broadcast via shared memory (STS.32 + 8 uniform LDS.128, double
//   buffered, one __syncwarp per step) instead of 32-64 shfls.
// - Gates via MUFU tanh.approx (sigmoid = 0.5*tanh(x/2)+0.5).
// ---------------------------------------------------------------------------

#define B_ROWS 4096
#define SEQ    512
#define HID    32

typedef unsigned long long ull;

// 4096*512*32 floats = 268 MB scratch for h1
__device__ float g_h1[(size_t)B_ROWS * SEQ * HID];

__device__ __forceinline__ ull ffma2(ull a, ull b, ull c) {
    ull d;
    asm("fma.rn.f32x2 %0, %1, %2, %3;" : "=l"(d) : "l"(a), "l"(b), "l"(c));
    return d;
}
__device__ __forceinline__ float2 unpack2(ull v) {
    float2 r;
    asm("mov.b64 {%0, %1}, %2;" : "=f"(r.x), "=f"(r.y) : "l"(v));
    return r;
}
__device__ __forceinline__ float hsum2(ull v) {
    float2 r = unpack2(v);
    return r.x + r.y;
}
__device__ __forceinline__ float tanh_ap(float x) {
    float y;
    asm("tanh.approx.f32 %0, %1;" : "=f"(y) : "f"(x));
    return y;
}
__device__ __forceinline__ float sig_ap(float x) {
    return fmaf(0.5f, tanh_ap(0.5f * x), 0.5f);
}

// ---------------------------------------------------------------------------
// Pass 1: GRU layer 1.  x:[B,S,4] -> h1:[B,S,32]
// ---------------------------------------------------------------------------
__global__ __launch_bounds__(128)
void gru_layer1_kernel(const float* __restrict__ x,
                       const float* __restrict__ Wih,   // [96,4]
                       const float* __restrict__ Whh,   // [96,32]
                       const float* __restrict__ bih,   // [96]
                       const float* __restrict__ bhh)   // [96]
{
    __shared__ __align__(16) float hbuf[4][2][HID];

    const int warp   = (blockIdx.x * blockDim.x + threadIdx.x) >> 5;
    const int wl     = threadIdx.x >> 5;
    const int lane   = threadIdx.x & 31;
    if (warp >= B_ROWS) return;

    // Recurrent weight rows for this lane's 3 gate outputs, packed by j-pair.
    ull whr[16], whz[16], whn[16];
    {
        const ull* pr = reinterpret_cast<const ull*>(Whh + (lane)      * HID);
        const ull* pz = reinterpret_cast<const ull*>(Whh + (32 + lane) * HID);
        const ull* pn = reinterpret_cast<const ull*>(Whh + (64 + lane) * HID);
#pragma unroll
        for (int k = 0; k < 16; k++) { whr[k] = pr[k]; whz[k] = pz[k]; whn[k] = pn[k]; }
    }
    const float4 wir = reinterpret_cast<const float4*>(Wih)[lane];
    const float4 wiz = reinterpret_cast<const float4*>(Wih)[32 + lane];
    const float4 win = reinterpret_cast<const float4*>(Wih)[64 + lane];

    const float br  = bih[lane]      + bhh[lane];
    const float bz  = bih[32 + lane] + bhh[32 + lane];
    const float bin = bih[64 + lane];
    const float bhn = bhh[64 + lane];

    const float4* xp = reinterpret_cast<const float4*>(x + (size_t)warp * SEQ * 4);
    float* op = g_h1 + (size_t)warp * SEQ * HID + lane;

    float h = 0.0f;
#pragma unroll 1
    for (int s = 0; s < SEQ; s++) {
        const float4 xv = __ldg(xp + s);

        // input contributions (scalar, only 4 wide)
        float ar = br, az = bz, xn = bin;
        ar = fmaf(wir.x, xv.x, ar); ar = fmaf(wir.y, xv.y, ar);
        ar = fmaf(wir.z, xv.z, ar); ar = fmaf(wir.w, xv.w, ar);
        az = fmaf(wiz.x, xv.x, az); az = fmaf(wiz.y, xv.y, az);
        az = fmaf(wiz.z, xv.z, az); az = fmaf(wiz.w, xv.w, az);
        xn = fmaf(win.x, xv.x, xn); xn = fmaf(win.y, xv.y, xn);
        xn = fmaf(win.z, xv.z, xn); xn = fmaf(win.w, xv.w, xn);

        // broadcast h through smem (double buffered)
        float* buf = hbuf[wl][s & 1];
        buf[lane] = h;
        __syncwarp();
        const ulonglong2* hp = reinterpret_cast<const ulonglong2*>(buf);

        ull accr = 0ull, accz = 0ull, accn = 0ull;
#pragma unroll
        for (int k = 0; k < 8; k++) {
            const ulonglong2 hv = hp[k];
            accr = ffma2(whr[2 * k],     hv.x, accr);
            accz = ffma2(whz[2 * k],     hv.x, accz);
            accn = ffma2(whn[2 * k],     hv.x, accn);
            accr = ffma2(whr[2 * k + 1], hv.y, accr);
            accz = ffma2(whz[2 * k + 1], hv.y, accz);
            accn = ffma2(whn[2 * k + 1], hv.y, accn);
        }
        ar += hsum2(accr);
        az += hsum2(accz);
        const float hn = bhn + hsum2(accn);

        const float r = sig_ap(ar);
        const float z = sig_ap(az);
        const float n = tanh_ap(fmaf(r, hn, xn));
        h = fmaf(z, h - n, n);

        op[(size_t)s * HID] = h;
    }
}

// ---------------------------------------------------------------------------
// Pass 2: GRU layer 2 + FC(32->32) + FC(32->1).  h1:[B,S,32] -> out:[B]
// ---------------------------------------------------------------------------
__global__ __launch_bounds__(128)
void gru_layer2_fc_kernel(const float* __restrict__ Wih,   // [96,32]
                          const float* __restrict__ Whh,   // [96,32]
                          const float* __restrict__ bih,   // [96]
                          const float* __restrict__ bhh,   // [96]
                          const float* __restrict__ Wfc2,  // [32,32]
                          const float* __restrict__ bfc2,  // [32]
                          const float* __restrict__ Wfc,   // [1,32]
                          const float* __restrict__ bfc,   // [1]
                          float* __restrict__ out)
{
    __shared__ __align__(16) float hbuf[4][2][HID];

    const int warp = (blockIdx.x * blockDim.x + threadIdx.x) >> 5;
    const int wl   = threadIdx.x >> 5;
    const int lane = threadIdx.x & 31;
    if (warp >= B_ROWS) return;

    ull wir[16], wiz[16], win[16], whr[16], whz[16], whn[16];
    {
        const ull* p0 = reinterpret_cast<const ull*>(Wih + (lane)      * HID);
        const ull* p1 = reinterpret_cast<const ull*>(Wih + (32 + lane) * HID);
        const ull* p2 = reinterpret_cast<const ull*>(Wih + (64 + lane) * HID);
        const ull* p3 = reinterpret_cast<const ull*>(Whh + (lane)      * HID);
        const ull* p4 = reinterpret_cast<const ull*>(Whh + (32 + lane) * HID);
        const ull* p5 = reinterpret_cast<const ull*>(Whh + (64 + lane) * HID);
#pragma unroll
        for (int k = 0; k < 16; k++) {
            wir[k] = p0[k]; wiz[k] = p1[k]; win[k] = p2[k];
            whr[k] = p3[k]; whz[k] = p4[k]; whn[k] = p5[k];
        }
    }
    const float br  = bih[lane]      + bhh[lane];
    const float bz  = bih[32 + lane] + bhh[32 + lane];
    const float bin = bih[64 + lane];
    const float bhn = bhh[64 + lane];

    const ulonglong2* xrow =
        reinterpret_cast<const ulonglong2*>(g_h1 + (size_t)warp * SEQ * HID);

    float h = 0.0f;
#pragma unroll 1
    for (int s = 0; s < SEQ; s++) {
        // broadcast recurrent h through smem (double buffered)
        float* buf = hbuf[wl][s & 1];
        buf[lane] = h;
        __syncwarp();
        const ulonglong2* hp = reinterpret_cast<const ulonglong2*>(buf);
        const ulonglong2* xp = xrow + (size_t)s * 8;  // h1 row, packed pairs

        ull ar2 = 0ull, az2 = 0ull, axn = 0ull, ahn = 0ull;
#pragma unroll
        for (int k = 0; k < 8; k++) {
            const ulonglong2 xv = xp[k];   // uniform LDG.128 (L1 broadcast)
            const ulonglong2 hv = hp[k];
            ar2 = ffma2(wir[2 * k],     xv.x, ar2);
            az2 = ffma2(wiz[2 * k],     xv.x, az2);
            axn = ffma2(win[2 * k],     xv.x, axn);
            ar2 = ffma2(whr[2 * k],     hv.x, ar2);
            az2 = ffma2(whz[2 * k],     hv.x, az2);
            ahn = ffma2(whn[2 * k],     hv.x, ahn);
            ar2 = ffma2(wir[2 * k + 1], xv.y, ar2);
            az2 = ffma2(wiz[2 * k + 1], xv.y, az2);
            axn = ffma2(win[2 * k + 1], xv.y, axn);
            ar2 = ffma2(whr[2 * k + 1], hv.y, ar2);
            az2 = ffma2(whz[2 * k + 1], hv.y, az2);
            ahn = ffma2(whn[2 * k + 1], hv.y, ahn);
        }
        const float ar = br  + hsum2(ar2);
        const float az = bz  + hsum2(az2);
        const float xn = bin + hsum2(axn);
        const float hn = bhn + hsum2(ahn);

        const float r = sig_ap(ar);
        const float z = sig_ap(az);
        const float n = tanh_ap(fmaf(r, hn, xn));
        h = fmaf(z, h - n, n);
    }

    // FC2: o[lane] = W_fc2[lane,:] . h + b_fc2[lane]  (reuse smem broadcast)
    {
        float* buf = hbuf[wl][0];
        buf[lane] = h;
        __syncwarp();
        const ulonglong2* hp = reinterpret_cast<const ulonglong2*>(buf);
        const ull* wf = reinterpret_cast<const ull*>(Wfc2 + lane * HID);
        ull acc = 0ull;
#pragma unroll
        for (int k = 0; k < 8; k++) {
            const ulonglong2 hv = hp[k];
            acc = ffma2(wf[2 * k],     hv.x, acc);
            acc = ffma2(wf[2 * k + 1], hv.y, acc);
        }
        const float o = __ldg(bfc2 + lane) + hsum2(acc);

        // FC: scalar = W_fc[0,:] . o + b_fc[0]
        float p = __ldg(Wfc + lane) * o;
#pragma unroll
        for (int off = 16; off > 0; off >>= 1)
            p += __shfl_xor_sync(0xffffffffu, p, off);
        if (lane == 0) out[warp] = p + __ldg(bfc);
    }
}

// ---------------------------------------------------------------------------
// Launch
// ---------------------------------------------------------------------------
extern "C" void kernel_launch(void* const* d_in, const int* in_sizes, int n_in,
                              void* d_out, int out_size)
{
    const float* x     = (const float*)d_in[0];
    const float* Wih0  = (const float*)d_in[1];
    const float* Whh0  = (const float*)d_in[2];
    const float* bih0  = (const float*)d_in[3];
    const float* bhh0  = (const float*)d_in[4];
    const float* Wih1  = (const float*)d_in[5];
    const float* Whh1  = (const float*)d_in[6];
    const float* bih1  = (const float*)d_in[7];
    const float* bhh1  = (const float*)d_in[8];
    const float* Wfc2  = (const float*)d_in[9];
    const float* bfc2  = (const float*)d_in[10];
    const float* Wfc   = (const float*)d_in[11];
    const float* bfc   = (const float*)d_in[12];
    float* out = (float*)d_out;

    const int threads = 128;
    const int blocks  = B_ROWS / (threads / 32);

    gru_layer1_kernel<<<blocks, threads>>>(x, Wih0, Whh0, bih0, bhh0);
    gru_layer2_fc_kernel<<<blocks, threads>>>(Wih1, Whh1, bih1, bhh1,
                                              Wfc2, bfc2, Wfc, bfc, out);
}

// round 5
// speedup vs baseline: 1.6387x; 1.6387x over previous
#include <cuda_runtime.h>
#include <cuda_bf16.h>
#include <cstdint>

// ---------------------------------------------------------------------------
// 2-layer GRU (H=32, INPUT=4, B=4096, S=512) + FC(32->32) + FC(32->1)
//
// Warp per batch row, lane per hidden unit.
// - Packed fma.rn.f32x2 gate dot products (weights register-resident).
// - h broadcast via smem double buffer, one __syncwarp per step.
// - NEW: per-warp cp.async ring (depth 8) stages the per-step input row
//   (x for layer 1, h1 for layer 2) into smem 8 steps ahead, hiding the
//   DRAM latency that dominated the previous version.
// ---------------------------------------------------------------------------

#define B_ROWS 4096
#define SEQ    512
#define HID    32
#define RING   8          // prefetch distance (steps)

typedef unsigned long long ull;

// 4096*512*32 floats = 268 MB scratch for h1
__device__ float g_h1[(size_t)B_ROWS * SEQ * HID];

__device__ __forceinline__ ull ffma2(ull a, ull b, ull c) {
    ull d;
    asm("fma.rn.f32x2 %0, %1, %2, %3;" : "=l"(d) : "l"(a), "l"(b), "l"(c));
    return d;
}
__device__ __forceinline__ float hsum2(ull v) {
    float2 r;
    asm("mov.b64 {%0, %1}, %2;" : "=f"(r.x), "=f"(r.y) : "l"(v));
    return r.x + r.y;
}
__device__ __forceinline__ float tanh_ap(float x) {
    float y;
    asm("tanh.approx.f32 %0, %1;" : "=f"(y) : "f"(x));
    return y;
}
__device__ __forceinline__ float sig_ap(float x) {
    return fmaf(0.5f, tanh_ap(0.5f * x), 0.5f);
}
__device__ __forceinline__ void cp_async4(uint32_t smem_addr, const float* gptr) {
    asm volatile("cp.async.ca.shared.global [%0], [%1], 4;"
                 :: "r"(smem_addr), "l"(gptr));
}
__device__ __forceinline__ void cp_commit() {
    asm volatile("cp.async.commit_group;");
}
__device__ __forceinline__ void cp_wait_ring() {
    asm volatile("cp.async.wait_group %0;" :: "n"(RING - 1));
}

// ---------------------------------------------------------------------------
// Pass 1: GRU layer 1.  x:[B,S,4] -> h1:[B,S,32]
// ---------------------------------------------------------------------------
__global__ __launch_bounds__(128)
void gru_layer1_kernel(const float* __restrict__ x,
                       const float* __restrict__ Wih,   // [96,4]
                       const float* __restrict__ Whh,   // [96,32]
                       const float* __restrict__ bih,   // [96]
                       const float* __restrict__ bhh)   // [96]
{
    __shared__ __align__(16) float hbuf[4][2][HID];
    __shared__ __align__(16) float xring[4][RING][4];   // 16B rows

    const int warp = (blockIdx.x * blockDim.x + threadIdx.x) >> 5;
    const int wl   = threadIdx.x >> 5;
    const int lane = threadIdx.x & 31;
    if (warp >= B_ROWS) return;

    ull whr[16], whz[16], whn[16];
    {
        const ull* pr = reinterpret_cast<const ull*>(Whh + (lane)      * HID);
        const ull* pz = reinterpret_cast<const ull*>(Whh + (32 + lane) * HID);
        const ull* pn = reinterpret_cast<const ull*>(Whh + (64 + lane) * HID);
#pragma unroll
        for (int k = 0; k < 16; k++) { whr[k] = pr[k]; whz[k] = pz[k]; whn[k] = pn[k]; }
    }
    const float4 wir = reinterpret_cast<const float4*>(Wih)[lane];
    const float4 wiz = reinterpret_cast<const float4*>(Wih)[32 + lane];
    const float4 win = reinterpret_cast<const float4*>(Wih)[64 + lane];

    const float br  = bih[lane]      + bhh[lane];
    const float bz  = bih[32 + lane] + bhh[32 + lane];
    const float bin = bih[64 + lane];
    const float bhn = bhh[64 + lane];

    const float* xsrc = x + (size_t)warp * SEQ * 4;          // 4 floats/step
    float* op = g_h1 + (size_t)warp * SEQ * HID + lane;

    const uint32_t ring_base =
        (uint32_t)__cvta_generic_to_shared(&xring[wl][0][0]);

    // Prologue: stage rows 0..RING-1 (lanes 0..3 carry 4B each)
#pragma unroll
    for (int d = 0; d < RING; d++) {
        if (lane < 4) cp_async4(ring_base + d * 16 + lane * 4, xsrc + d * 4 + lane);
        cp_commit();
    }

    float h = 0.0f;
#pragma unroll 1
    for (int s = 0; s < SEQ; s++) {
        hbuf[wl][s & 1][lane] = h;          // h broadcast (double buffered)
        cp_wait_ring();
        __syncwarp();                       // covers ring row s AND hbuf

        const float4 xv =
            *reinterpret_cast<const float4*>(&xring[wl][s & RING - 1][0]);
        const ulonglong2* hp =
            reinterpret_cast<const ulonglong2*>(&hbuf[wl][s & 1][0]);

        // prefetch row s+RING
        if (lane < 4 && s + RING < SEQ)
            cp_async4(ring_base + ((s + RING) & (RING - 1)) * 16 + lane * 4,
                      xsrc + (s + RING) * 4 + lane);
        cp_commit();

        float ar = br, az = bz, xn = bin;
        ar = fmaf(wir.x, xv.x, ar); ar = fmaf(wir.y, xv.y, ar);
        ar = fmaf(wir.z, xv.z, ar); ar = fmaf(wir.w, xv.w, ar);
        az = fmaf(wiz.x, xv.x, az); az = fmaf(wiz.y, xv.y, az);
        az = fmaf(wiz.z, xv.z, az); az = fmaf(wiz.w, xv.w, az);
        xn = fmaf(win.x, xv.x, xn); xn = fmaf(win.y, xv.y, xn);
        xn = fmaf(win.z, xv.z, xn); xn = fmaf(win.w, xv.w, xn);

        ull accr = 0ull, accz = 0ull, accn = 0ull;
#pragma unroll
        for (int k = 0; k < 8; k++) {
            const ulonglong2 hv = hp[k];
            accr = ffma2(whr[2 * k],     hv.x, accr);
            accz = ffma2(whz[2 * k],     hv.x, accz);
            accn = ffma2(whn[2 * k],     hv.x, accn);
            accr = ffma2(whr[2 * k + 1], hv.y, accr);
            accz = ffma2(whz[2 * k + 1], hv.y, accz);
            accn = ffma2(whn[2 * k + 1], hv.y, accn);
        }
        ar += hsum2(accr);
        az += hsum2(accz);
        const float hn = bhn + hsum2(accn);

        const float r = sig_ap(ar);
        const float z = sig_ap(az);
        const float n = tanh_ap(fmaf(r, hn, xn));
        h = fmaf(z, h - n, n);

        op[(size_t)s * HID] = h;
    }
}

// ---------------------------------------------------------------------------
// Pass 2: GRU layer 2 + FC(32->32) + FC(32->1).  h1:[B,S,32] -> out:[B]
// ---------------------------------------------------------------------------
__global__ __launch_bounds__(128)
void gru_layer2_fc_kernel(const float* __restrict__ Wih,   // [96,32]
                          const float* __restrict__ Whh,   // [96,32]
                          const float* __restrict__ bih,   // [96]
                          const float* __restrict__ bhh,   // [96]
                          const float* __restrict__ Wfc2,  // [32,32]
                          const float* __restrict__ bfc2,  // [32]
                          const float* __restrict__ Wfc,   // [1,32]
                          const float* __restrict__ bfc,   // [1]
                          float* __restrict__ out)
{
    __shared__ __align__(16) float hbuf[4][2][HID];
    __shared__ __align__(16) float xring[4][RING][HID];    // 128B rows

    const int warp = (blockIdx.x * blockDim.x + threadIdx.x) >> 5;
    const int wl   = threadIdx.x >> 5;
    const int lane = threadIdx.x & 31;
    if (warp >= B_ROWS) return;

    ull wir[16], wiz[16], win[16], whr[16], whz[16], whn[16];
    {
        const ull* p0 = reinterpret_cast<const ull*>(Wih + (lane)      * HID);
        const ull* p1 = reinterpret_cast<const ull*>(Wih + (32 + lane) * HID);
        const ull* p2 = reinterpret_cast<const ull*>(Wih + (64 + lane) * HID);
        const ull* p3 = reinterpret_cast<const ull*>(Whh + (lane)      * HID);
        const ull* p4 = reinterpret_cast<const ull*>(Whh + (32 + lane) * HID);
        const ull* p5 = reinterpret_cast<const ull*>(Whh + (64 + lane) * HID);
#pragma unroll
        for (int k = 0; k < 16; k++) {
            wir[k] = p0[k]; wiz[k] = p1[k]; win[k] = p2[k];
            whr[k] = p3[k]; whz[k] = p4[k]; whn[k] = p5[k];
        }
    }
    const float br  = bih[lane]      + bhh[lane];
    const float bz  = bih[32 + lane] + bhh[32 + lane];
    const float bin = bih[64 + lane];
    const float bhn = bhh[64 + lane];

    const float* xsrc = g_h1 + (size_t)warp * SEQ * HID;   // 32 floats/step

    const uint32_t ring_base =
        (uint32_t)__cvta_generic_to_shared(&xring[wl][0][0]);

    // Prologue: stage rows 0..RING-1 (each lane carries 4B of the 128B row)
#pragma unroll
    for (int d = 0; d < RING; d++) {
        cp_async4(ring_base + d * 128 + lane * 4, xsrc + d * HID + lane);
        cp_commit();
    }

    float h = 0.0f;
#pragma unroll 1
    for (int s = 0; s < SEQ; s++) {
        hbuf[wl][s & 1][lane] = h;
        cp_wait_ring();
        __syncwarp();

        const ulonglong2* xp =
            reinterpret_cast<const ulonglong2*>(&xring[wl][s & (RING - 1)][0]);
        const ulonglong2* hp =
            reinterpret_cast<const ulonglong2*>(&hbuf[wl][s & 1][0]);

        // prefetch row s+RING
        if (s + RING < SEQ)
            cp_async4(ring_base + ((s + RING) & (RING - 1)) * 128 + lane * 4,
                      xsrc + (s + RING) * HID + lane);
        cp_commit();

        ull ar2 = 0ull, az2 = 0ull, axn = 0ull, ahn = 0ull;
#pragma unroll
        for (int k = 0; k < 8; k++) {
            const ulonglong2 xv = xp[k];
            const ulonglong2 hv = hp[k];
            ar2 = ffma2(wir[2 * k],     xv.x, ar2);
            az2 = ffma2(wiz[2 * k],     xv.x, az2);
            axn = ffma2(win[2 * k],     xv.x, axn);
            ar2 = ffma2(whr[2 * k],     hv.x, ar2);
            az2 = ffma2(whz[2 * k],     hv.x, az2);
            ahn = ffma2(whn[2 * k],     hv.x, ahn);
            ar2 = ffma2(wir[2 * k + 1], xv.y, ar2);
            az2 = ffma2(wiz[2 * k + 1], xv.y, az2);
            axn = ffma2(win[2 * k + 1], xv.y, axn);
            ar2 = ffma2(whr[2 * k + 1], hv.y, ar2);
            az2 = ffma2(whz[2 * k + 1], hv.y, az2);
            ahn = ffma2(whn[2 * k + 1], hv.y, ahn);
        }
        const float ar = br  + hsum2(ar2);
        const float az = bz  + hsum2(az2);
        const float xn = bin + hsum2(axn);
        const float hn = bhn + hsum2(ahn);

        const float r = sig_ap(ar);
        const float z = sig_ap(az);
        const float n = tanh_ap(fmaf(r, hn, xn));
        h = fmaf(z, h - n, n);
    }

    // FC2 + FC epilogue
    {
        hbuf[wl][0][lane] = h;
        __syncwarp();
        const ulonglong2* hp = reinterpret_cast<const ulonglong2*>(&hbuf[wl][0][0]);
        const ull* wf = reinterpret_cast<const ull*>(Wfc2 + lane * HID);
        ull acc = 0ull;
#pragma unroll
        for (int k = 0; k < 8; k++) {
            const ulonglong2 hv = hp[k];
            acc = ffma2(wf[2 * k],     hv.x, acc);
            acc = ffma2(wf[2 * k + 1], hv.y, acc);
        }
        const float o = __ldg(bfc2 + lane) + hsum2(acc);

        float p = __ldg(Wfc + lane) * o;
#pragma unroll
        for (int off = 16; off > 0; off >>= 1)
            p += __shfl_xor_sync(0xffffffffu, p, off);
        if (lane == 0) out[warp] = p + __ldg(bfc);
    }
}

// ---------------------------------------------------------------------------
// Launch
// ---------------------------------------------------------------------------
extern "C" void kernel_launch(void* const* d_in, const int* in_sizes, int n_in,
                              void* d_out, int out_size)
{
    const float* x     = (const float*)d_in[0];
    const float* Wih0  = (const float*)d_in[1];
    const float* Whh0  = (const float*)d_in[2];
    const float* bih0  = (const float*)d_in[3];
    const float* bhh0  = (const float*)d_in[4];
    const float* Wih1  = (const float*)d_in[5];
    const float* Whh1  = (const float*)d_in[6];
    const float* bih1  = (const float*)d_in[7];
    const float* bhh1  = (const float*)d_in[8];
    const float* Wfc2  = (const float*)d_in[9];
    const float* bfc2  = (const float*)d_in[10];
    const float* Wfc   = (const float*)d_in[11];
    const float* bfc   = (const float*)d_in[12];
    float* out = (float*)d_out;

    const int threads = 128;
    const int blocks  = B_ROWS / (threads / 32);

    gru_layer1_kernel<<<blocks, threads>>>(x, Wih0, Whh0, bih0, bhh0);
    gru_layer2_fc_kernel<<<blocks, threads>>>(Wih1, Whh1, bih1, bhh1,
                                              Wfc2, bfc2, Wfc, bfc, out);
}

// round 6
// speedup vs baseline: 1.6447x; 1.0037x over previous
#include <cuda_runtime.h>
#include <cuda_bf16.h>
#include <cstdint>

// ---------------------------------------------------------------------------
// 2-layer GRU (H=32, INPUT=4, B=4096, S=512) + FC(32->32) + FC(32->1)
//
// Warp per batch row, lane per hidden unit.
// - Packed fma.rn.f32x2 gate dot products (weights register-resident).
// - h broadcast via smem double buffer, one __syncwarp per step.
// - NEW: per-warp cp.async ring (depth 8) stages the per-step input row
//   (x for layer 1, h1 for layer 2) into smem 8 steps ahead, hiding the
//   DRAM latency that dominated the previous version.
// ---------------------------------------------------------------------------

#define B_ROWS 4096
#define SEQ    512
#define HID    32
#define RING   8          // prefetch distance (steps)

typedef unsigned long long ull;

// 4096*512*32 floats = 268 MB scratch for h1
__device__ float g_h1[(size_t)B_ROWS * SEQ * HID];

__device__ __forceinline__ ull ffma2(ull a, ull b, ull c) {
    ull d;
    asm("fma.rn.f32x2 %0, %1, %2, %3;" : "=l"(d) : "l"(a), "l"(b), "l"(c));
    return d;
}
__device__ __forceinline__ float hsum2(ull v) {
    float2 r;
    asm("mov.b64 {%0, %1}, %2;" : "=f"(r.x), "=f"(r.y) : "l"(v));
    return r.x + r.y;
}
__device__ __forceinline__ float tanh_ap(float x) {
    float y;
    asm("tanh.approx.f32 %0, %1;" : "=f"(y) : "f"(x));
    return y;
}
__device__ __forceinline__ float sig_ap(float x) {
    return fmaf(0.5f, tanh_ap(0.5f * x), 0.5f);
}
__device__ __forceinline__ void cp_async4(uint32_t smem_addr, const float* gptr) {
    asm volatile("cp.async.ca.shared.global [%0], [%1], 4;"
                 :: "r"(smem_addr), "l"(gptr));
}
__device__ __forceinline__ void cp_commit() {
    asm volatile("cp.async.commit_group;");
}
__device__ __forceinline__ void cp_wait_ring() {
    asm volatile("cp.async.wait_group %0;" :: "n"(RING - 1));
}

// ---------------------------------------------------------------------------
// Pass 1: GRU layer 1.  x:[B,S,4] -> h1:[B,S,32]
// ---------------------------------------------------------------------------
__global__ __launch_bounds__(128)
void gru_layer1_kernel(const float* __restrict__ x,
                       const float* __restrict__ Wih,   // [96,4]
                       const float* __restrict__ Whh,   // [96,32]
                       const float* __restrict__ bih,   // [96]
                       const float* __restrict__ bhh)   // [96]
{
    __shared__ __align__(16) float hbuf[4][2][HID];
    __shared__ __align__(16) float xring[4][RING][4];   // 16B rows

    const int warp = (blockIdx.x * blockDim.x + threadIdx.x) >> 5;
    const int wl   = threadIdx.x >> 5;
    const int lane = threadIdx.x & 31;
    if (warp >= B_ROWS) return;

    ull whr[16], whz[16], whn[16];
    {
        const ull* pr = reinterpret_cast<const ull*>(Whh + (lane)      * HID);
        const ull* pz = reinterpret_cast<const ull*>(Whh + (32 + lane) * HID);
        const ull* pn = reinterpret_cast<const ull*>(Whh + (64 + lane) * HID);
#pragma unroll
        for (int k = 0; k < 16; k++) { whr[k] = pr[k]; whz[k] = pz[k]; whn[k] = pn[k]; }
    }
    const float4 wir = reinterpret_cast<const float4*>(Wih)[lane];
    const float4 wiz = reinterpret_cast<const float4*>(Wih)[32 + lane];
    const float4 win = reinterpret_cast<const float4*>(Wih)[64 + lane];

    const float br  = bih[lane]      + bhh[lane];
    const float bz  = bih[32 + lane] + bhh[32 + lane];
    const float bin = bih[64 + lane];
    const float bhn = bhh[64 + lane];

    const float* xsrc = x + (size_t)warp * SEQ * 4;          // 4 floats/step
    float* op = g_h1 + (size_t)warp * SEQ * HID + lane;

    const uint32_t ring_base =
        (uint32_t)__cvta_generic_to_shared(&xring[wl][0][0]);

    // Prologue: stage rows 0..RING-1 (lanes 0..3 carry 4B each)
#pragma unroll
    for (int d = 0; d < RING; d++) {
        if (lane < 4) cp_async4(ring_base + d * 16 + lane * 4, xsrc + d * 4 + lane);
        cp_commit();
    }

    float h = 0.0f;
#pragma unroll 1
    for (int s = 0; s < SEQ; s++) {
        hbuf[wl][s & 1][lane] = h;          // h broadcast (double buffered)
        cp_wait_ring();
        __syncwarp();                       // covers ring row s AND hbuf

        const float4 xv =
            *reinterpret_cast<const float4*>(&xring[wl][s & RING - 1][0]);
        const ulonglong2* hp =
            reinterpret_cast<const ulonglong2*>(&hbuf[wl][s & 1][0]);

        // prefetch row s+RING
        if (lane < 4 && s + RING < SEQ)
            cp_async4(ring_base + ((s + RING) & (RING - 1)) * 16 + lane * 4,
                      xsrc + (s + RING) * 4 + lane);
        cp_commit();

        float ar = br, az = bz, xn = bin;
        ar = fmaf(wir.x, xv.x, ar); ar = fmaf(wir.y, xv.y, ar);
        ar = fmaf(wir.z, xv.z, ar); ar = fmaf(wir.w, xv.w, ar);
        az = fmaf(wiz.x, xv.x, az); az = fmaf(wiz.y, xv.y, az);
        az = fmaf(wiz.z, xv.z, az); az = fmaf(wiz.w, xv.w, az);
        xn = fmaf(win.x, xv.x, xn); xn = fmaf(win.y, xv.y, xn);
        xn = fmaf(win.z, xv.z, xn); xn = fmaf(win.w, xv.w, xn);

        ull accr = 0ull, accz = 0ull, accn = 0ull;
#pragma unroll
        for (int k = 0; k < 8; k++) {
            const ulonglong2 hv = hp[k];
            accr = ffma2(whr[2 * k],     hv.x, accr);
            accz = ffma2(whz[2 * k],     hv.x, accz);
            accn = ffma2(whn[2 * k],     hv.x, accn);
            accr = ffma2(whr[2 * k + 1], hv.y, accr);
            accz = ffma2(whz[2 * k + 1], hv.y, accz);
            accn = ffma2(whn[2 * k + 1], hv.y, accn);
        }
        ar += hsum2(accr);
        az += hsum2(accz);
        const float hn = bhn + hsum2(accn);

        const float r = sig_ap(ar);
        const float z = sig_ap(az);
        const float n = tanh_ap(fmaf(r, hn, xn));
        h = fmaf(z, h - n, n);

        op[(size_t)s * HID] = h;
    }
}

// ---------------------------------------------------------------------------
// Pass 2: GRU layer 2 + FC(32->32) + FC(32->1).  h1:[B,S,32] -> out:[B]
// ---------------------------------------------------------------------------
__global__ __launch_bounds__(128)
void gru_layer2_fc_kernel(const float* __restrict__ Wih,   // [96,32]
                          const float* __restrict__ Whh,   // [96,32]
                          const float* __restrict__ bih,   // [96]
                          const float* __restrict__ bhh,   // [96]
                          const float* __restrict__ Wfc2,  // [32,32]
                          const float* __restrict__ bfc2,  // [32]
                          const float* __restrict__ Wfc,   // [1,32]
                          const float* __restrict__ bfc,   // [1]
                          float* __restrict__ out)
{
    __shared__ __align__(16) float hbuf[4][2][HID];
    __shared__ __align__(16) float xring[4][RING][HID];    // 128B rows

    const int warp = (blockIdx.x * blockDim.x + threadIdx.x) >> 5;
    const int wl   = threadIdx.x >> 5;
    const int lane = threadIdx.x & 31;
    if (warp >= B_ROWS) return;

    ull wir[16], wiz[16], win[16], whr[16], whz[16], whn[16];
    {
        const ull* p0 = reinterpret_cast<const ull*>(Wih + (lane)      * HID);
        const ull* p1 = reinterpret_cast<const ull*>(Wih + (32 + lane) * HID);
        const ull* p2 = reinterpret_cast<const ull*>(Wih + (64 + lane) * HID);
        const ull* p3 = reinterpret_cast<const ull*>(Whh + (lane)      * HID);
        const ull* p4 = reinterpret_cast<const ull*>(Whh + (32 + lane) * HID);
        const ull* p5 = reinterpret_cast<const ull*>(Whh + (64 + lane) * HID);
#pragma unroll
        for (int k = 0; k < 16; k++) {
            wir[k] = p0[k]; wiz[k] = p1[k]; win[k] = p2[k];
            whr[k] = p3[k]; whz[k] = p4[k]; whn[k] = p5[k];
        }
    }
    const float br  = bih[lane]      + bhh[lane];
    const float bz  = bih[32 + lane] + bhh[32 + lane];
    const float bin = bih[64 + lane];
    const float bhn = bhh[64 + lane];

    const float* xsrc = g_h1 + (size_t)warp * SEQ * HID;   // 32 floats/step

    const uint32_t ring_base =
        (uint32_t)__cvta_generic_to_shared(&xring[wl][0][0]);

    // Prologue: stage rows 0..RING-1 (each lane carries 4B of the 128B row)
#pragma unroll
    for (int d = 0; d < RING; d++) {
        cp_async4(ring_base + d * 128 + lane * 4, xsrc + d * HID + lane);
        cp_commit();
    }

    float h = 0.0f;
#pragma unroll 1
    for (int s = 0; s < SEQ; s++) {
        hbuf[wl][s & 1][lane] = h;
        cp_wait_ring();
        __syncwarp();

        const ulonglong2* xp =
            reinterpret_cast<const ulonglong2*>(&xring[wl][s & (RING - 1)][0]);
        const ulonglong2* hp =
            reinterpret_cast<const ulonglong2*>(&hbuf[wl][s & 1][0]);

        // prefetch row s+RING
        if (s + RING < SEQ)
            cp_async4(ring_base + ((s + RING) & (RING - 1)) * 128 + lane * 4,
                      xsrc + (s + RING) * HID + lane);
        cp_commit();

        ull ar2 = 0ull, az2 = 0ull, axn = 0ull, ahn = 0ull;
#pragma unroll
        for (int k = 0; k < 8; k++) {
            const ulonglong2 xv = xp[k];
            const ulonglong2 hv = hp[k];
            ar2 = ffma2(wir[2 * k],     xv.x, ar2);
            az2 = ffma2(wiz[2 * k],     xv.x, az2);
            axn = ffma2(win[2 * k],     xv.x, axn);
            ar2 = ffma2(whr[2 * k],     hv.x, ar2);
            az2 = ffma2(whz[2 * k],     hv.x, az2);
            ahn = ffma2(whn[2 * k],     hv.x, ahn);
            ar2 = ffma2(wir[2 * k + 1], xv.y, ar2);
            az2 = ffma2(wiz[2 * k + 1], xv.y, az2);
            axn = ffma2(win[2 * k + 1], xv.y, axn);
            ar2 = ffma2(whr[2 * k + 1], hv.y, ar2);
            az2 = ffma2(whz[2 * k + 1], hv.y, az2);
            ahn = ffma2(whn[2 * k + 1], hv.y, ahn);
        }
        const float ar = br  + hsum2(ar2);
        const float az = bz  + hsum2(az2);
        const float xn = bin + hsum2(axn);
        const float hn = bhn + hsum2(ahn);

        const float r = sig_ap(ar);
        const float z = sig_ap(az);
        const float n = tanh_ap(fmaf(r, hn, xn));
        h = fmaf(z, h - n, n);
    }

    // FC2 + FC epilogue
    {
        hbuf[wl][0][lane] = h;
        __syncwarp();
        const ulonglong2* hp = reinterpret_cast<const ulonglong2*>(&hbuf[wl][0][0]);
        const ull* wf = reinterpret_cast<const ull*>(Wfc2 + lane * HID);
        ull acc = 0ull;
#pragma unroll
        for (int k = 0; k < 8; k++) {
            const ulonglong2 hv = hp[k];
            acc = ffma2(wf[2 * k],     hv.x, acc);
            acc = ffma2(wf[2 * k + 1], hv.y, acc);
        }
        const float o = __ldg(bfc2 + lane) + hsum2(acc);

        float p = __ldg(Wfc + lane) * o;
#pragma unroll
        for (int off = 16; off > 0; off >>= 1)
            p += __shfl_xor_sync(0xffffffffu, p, off);
        if (lane == 0) out[warp] = p + __ldg(bfc);
    }
}

// ---------------------------------------------------------------------------
// Launch
// ---------------------------------------------------------------------------
extern "C" void kernel_launch(void* const* d_in, const int* in_sizes, int n_in,
                              void* d_out, int out_size)
{
    const float* x     = (const float*)d_in[0];
    const float* Wih0  = (const float*)d_in[1];
    const float* Whh0  = (const float*)d_in[2];
    const float* bih0  = (const float*)d_in[3];
    const float* bhh0  = (const float*)d_in[4];
    const float* Wih1  = (const float*)d_in[5];
    const float* Whh1  = (const float*)d_in[6];
    const float* bih1  = (const float*)d_in[7];
    const float* bhh1  = (const float*)d_in[8];
    const float* Wfc2  = (const float*)d_in[9];
    const float* bfc2  = (const float*)d_in[10];
    const float* Wfc   = (const float*)d_in[11];
    const float* bfc   = (const float*)d_in[12];
    float* out = (float*)d_out;

    const int threads = 128;
    const int blocks  = B_ROWS / (threads / 32);

    gru_layer1_kernel<<<blocks, threads>>>(x, Wih0, Whh0, bih0, bhh0);
    gru_layer2_fc_kernel<<<blocks, threads>>>(Wih1, Whh1, bih1, bhh1,
                                              Wfc2, bfc2, Wfc, bfc, out);
}